// round 2
// baseline (speedup 1.0000x reference)
#include <cuda_runtime.h>
#include <math.h>

#define NSPEC  256
#define NSPEC3 5456

// scratch (static device globals — allowed)
__device__ float2 g_fhat[NSPEC*16*16];    // [s][b][i]
__device__ float2 g_psi [NSPEC*16*64];    // [s][i][o]
__device__ float2 g_Fz  [16*64*NSPEC3];   // [b*64+o][e]  (44.7 MB)

__constant__ int c_offs[16] = {0,1,10,35,84,165,286,455,680,969,1330,1771,2300,2925,3654,4495};

// ---------------- Kernel 1: fhat[s,b,f] = sum_j wig_s2[j,s] * DFT_alpha(x)[b,f,j,m(s)] ----------------
__global__ void k_fhat(const float* __restrict__ x, const float* __restrict__ wig) {
    __shared__ float  sx[64*65];
    __shared__ float2 xf[64*31];       // [j][mt], mt = m+15, m in [-15,15]
    __shared__ float  c64[64], s64[64];
    int b = blockIdx.x, f = blockIdx.y, tid = threadIdx.x;
    if (tid < 64) { float sv, cv; sincospif((float)tid/32.0f, &sv, &cv); c64[tid]=cv; s64[tid]=sv; }
    const float* xp = x + (size_t)(b*16+f)*4096;
    for (int p = tid; p < 4096; p += 256) sx[(p>>6)*65 + (p&63)] = xp[p];
    __syncthreads();
    for (int p = tid; p < 1984; p += 256) {           // 31 m-values x 64 betas
        int mt = p >> 6, j = p & 63, m = mt - 15;
        float ar=0.f, ai=0.f;
        const float* row = &sx[j*65];
        #pragma unroll 8
        for (int a = 0; a < 64; a++) {
            int t = (m*a) & 63;                        // (m*a) mod 64 (two's complement & works)
            float v = row[a];
            ar += v*c64[t];                            // e^{-2pi i m a/64}
            ai -= v*s64[t];
        }
        xf[j*31+mt] = make_float2(ar, ai);
    }
    __syncthreads();
    int s = tid;                                       // 256 threads = 256 spec indices
    int l = (int)sqrtf((float)s);
    while ((l+1)*(l+1) <= s) ++l;
    while (l*l > s) --l;
    int mt = s - l*l - l + 15;
    float ar=0.f, ai=0.f;
    #pragma unroll 8
    for (int j = 0; j < 64; j++) {
        float w = wig[j*NSPEC + s];
        float2 v = xf[j*31+mt];
        ar += w*v.x; ai += w*v.y;
    }
    g_fhat[(s*16+b)*16+f] = make_float2(ar, ai);
}

// ---------------- Kernel 2: psi[s,i,o] = scaling * sum_g kernel[i,o,g] * Fk[s,g] ----------------
__global__ void k_psi(const float* __restrict__ kern, const float* __restrict__ fkr,
                      const float* __restrict__ fki, float scaling) {
    __shared__ float2 fk[32];
    int s = blockIdx.x, tid = threadIdx.x;
    if (tid < 32) fk[tid] = make_float2(fkr[s*32+tid]*scaling, fki[s*32+tid]*scaling);
    __syncthreads();
    for (int p = tid; p < 1024; p += 256) {            // p = i*64+o
        const float* kp = kern + p*32;
        float ar=0.f, ai=0.f;
        #pragma unroll
        for (int g = 0; g < 32; g++) { float kv = kp[g]; ar += kv*fk[g].x; ai += kv*fk[g].y; }
        g_psi[s*1024 + p] = make_float2(ar, ai);
    }
}

// ---------------- Kernel 3: Fz^l[b,o,m,n] = sum_i fhat[l^2+m,b,i] * conj(psi[l^2+n,i,o]) ----------------
__global__ void k_fz() {
    extern __shared__ float2 sm3[];
    float2* fh = sm3;          // [s*16+i] fhat slice for this b
    float2* ps = sm3 + 4096;   // [s*16+i] psi slice for this o
    int bo = blockIdx.x, b = bo >> 6, o = bo & 63, tid = threadIdx.x;
    for (int p = tid; p < 4096; p += 256) {
        int s = p >> 4, i = p & 15;
        fh[p] = g_fhat[(s*16+b)*16 + i];
        ps[p] = g_psi [(s*16+i)*64 + o];
    }
    __syncthreads();
    for (int e = tid; e < NSPEC3; e += 256) {
        int l = 15;
        while (c_offs[l] > e) --l;
        int L = 2*l+1;
        int r = e - c_offs[l];
        int mloc = r / L;
        int nloc = r - mloc*L;
        const float2* fp = &fh[(l*l + mloc)*16];
        const float2* pp = &ps[(l*l + nloc)*16];
        float ar=0.f, ai=0.f;
        #pragma unroll
        for (int i = 0; i < 16; i++) {
            float2 a = fp[i], c = pp[i];
            ar += a.x*c.x + a.y*c.y;                   // fhat * conj(psi)
            ai += a.y*c.x - a.x*c.y;
        }
        g_Fz[(size_t)bo*NSPEC3 + e] = make_float2(ar, ai);
    }
}

// ---------------- Kernel 4 (fused): spec plane + 2D inverse synthesis ----------------
// grid (1024 bo, 4 kq); each block handles 8 beta_out values.
// smem layout (float2 units): Fz 5456 | spc 962 (961 used, padded for 16B alignment of cs)
//                             | Vv 992 | cs 992 | wk (float 5456)
// total = (5456+962+992+992)*8 + 5456*4 = 67216 + 21824 = 89040 B
__global__ void k_main(const float* __restrict__ wig3, const float* __restrict__ bias,
                       float* __restrict__ out) {
    extern __shared__ float smraw[];
    float2* Fz  = (float2*)smraw;   // 5456
    float2* spc = Fz  + 5456;       // 962 (961 used)  [mi*31+ni]
    float2* Vv  = spc + 962;        // 992  [a*31+ni]
    float2* cs  = Vv  + 992;        // 992  cs[q*32+r] = e^{+2pi i (q-15) r / 32}; 16B-aligned
    float*  wk  = (float*)(cs + 992); // 5456
    int tid = threadIdx.x;
    int bo = blockIdx.x, o = bo & 63;
    int kq = blockIdx.y;
    int w = tid >> 5, lane = tid & 31;

    for (int p = tid; p < 992; p += 256) {
        int q = p >> 5, r = p & 31;
        int t = ((q-15)*r) & 31;
        float sv, cv; sincospif((float)t / 16.0f, &sv, &cv);
        cs[p] = make_float2(cv, sv);
    }
    for (int p = tid; p < NSPEC3; p += 256) Fz[p] = g_Fz[(size_t)bo*NSPEC3 + p];
    float bv = bias[o];

    for (int kk = 0; kk < 8; kk++) {
        int k = kq*8 + kk;
        __syncthreads();                                // protects wk/spc/Vv reuse + initial loads
        for (int p = tid; p < NSPEC3; p += 256) wk[p] = wig3[k*NSPEC3 + p];
        __syncthreads();

        // spec[m,n] = sum_{l>=max(|m|,|n|)} Fz^l[m,n] * d^l_k[m,n]
        for (int p = tid; p < 961; p += 256) {
            int mi = p / 31, ni = p - mi*31;
            int m = mi - 15, n = ni - 15;
            int am = m < 0 ? -m : m, an = n < 0 ? -n : n;
            int lmin = am > an ? am : an;
            float ar = 0.f, ai = 0.f;
            for (int l = lmin; l < 16; l++) {
                int idx = c_offs[l] + (m+l)*(2*l+1) + (n+l);
                float d = wk[idx];
                float2 fz = Fz[idx];
                ar += fz.x*d;
                ai += fz.y*d;
            }
            spc[p] = make_float2(ar, ai);
        }
        __syncthreads();

        // stage 1: V[a][n] = sum_m spec[m,n] e^{+2pi i m a/32}; warp w owns a in [4w,4w+4)
        {
            int a0 = w*4, ni = lane;
            float vr0=0,vi0=0,vr1=0,vi1=0,vr2=0,vi2=0,vr3=0,vi3=0;
            if (ni < 31) {
                const float4* cs4 = (const float4*)cs;
                for (int mi = 0; mi < 31; mi++) {
                    float2 sp = spc[mi*31+ni];
                    float4 eA = cs4[(mi*32+a0)>>1];     // (e0.x,e0.y,e1.x,e1.y) — broadcast
                    float4 eB = cs4[((mi*32+a0)>>1)+1]; // (e2, e3)
                    vr0 += sp.x*eA.x - sp.y*eA.y; vi0 += sp.x*eA.y + sp.y*eA.x;
                    vr1 += sp.x*eA.z - sp.y*eA.w; vi1 += sp.x*eA.w + sp.y*eA.z;
                    vr2 += sp.x*eB.x - sp.y*eB.y; vi2 += sp.x*eB.y + sp.y*eB.x;
                    vr3 += sp.x*eB.z - sp.y*eB.w; vi3 += sp.x*eB.w + sp.y*eB.z;
                }
                Vv[(a0+0)*31+ni] = make_float2(vr0,vi0);
                Vv[(a0+1)*31+ni] = make_float2(vr1,vi1);
                Vv[(a0+2)*31+ni] = make_float2(vr2,vi2);
                Vv[(a0+3)*31+ni] = make_float2(vr3,vi3);
            }
        }
        __syncthreads();

        // stage 2: out[a,g] = bias + Re( sum_n V[a][n] e^{+2pi i n g/32} ); lane=g (coalesced)
        {
            int a0 = w*4, g = lane;
            float acc0=bv, acc1=bv, acc2=bv, acc3=bv;
            for (int ni = 0; ni < 31; ni++) {
                float2 e  = cs[ni*32+g];
                float2 v0 = Vv[(a0+0)*31+ni];
                float2 v1 = Vv[(a0+1)*31+ni];
                float2 v2 = Vv[(a0+2)*31+ni];
                float2 v3 = Vv[(a0+3)*31+ni];
                acc0 += v0.x*e.x - v0.y*e.y;
                acc1 += v1.x*e.x - v1.y*e.y;
                acc2 += v2.x*e.x - v2.y*e.y;
                acc3 += v3.x*e.x - v3.y*e.y;
            }
            size_t base = ((size_t)bo*32 + k)*1024;
            out[base + (a0+0)*32 + g] = acc0;
            out[base + (a0+1)*32 + g] = acc1;
            out[base + (a0+2)*32 + g] = acc2;
            out[base + (a0+3)*32 + g] = acc3;
        }
    }
}

extern "C" void kernel_launch(void* const* d_in, const int* in_sizes, int n_in,
                              void* d_out, int out_size) {
    const float* x       = (const float*)d_in[0];
    const float* kern    = (const float*)d_in[1];
    const float* bias    = (const float*)d_in[2];
    const float* wig_s2  = (const float*)d_in[3];
    const float* fk_re   = (const float*)d_in[4];
    const float* fk_im   = (const float*)d_in[5];
    const float* wig_so3 = (const float*)d_in[6];
    float* out = (float*)d_out;

    // scaling = 1/sqrt(n_grid * f_in * b_out^4 / b_in^2) = 1/sqrt(32*16*16^4/32^2) = 1/sqrt(32768)
    float scaling = 1.0f / sqrtf(32768.0f);

    cudaFuncSetAttribute(k_fz,   cudaFuncAttributeMaxDynamicSharedMemorySize, 65536);
    cudaFuncSetAttribute(k_main, cudaFuncAttributeMaxDynamicSharedMemorySize, 89040);

    k_fhat<<<dim3(16,16), 256>>>(x, wig_s2);
    k_psi <<<256, 256>>>(kern, fk_re, fk_im, scaling);
    k_fz  <<<1024, 256, 65536>>>();
    k_main<<<dim3(1024, 4), 256, 89040>>>(wig_so3, bias, out);
}

// round 3
// speedup vs baseline: 2.1858x; 2.1858x over previous
#include <cuda_runtime.h>
#include <math.h>

#define NSPEC  256
#define NSPEC3 5456
#define NPACK  2856   // sum over l of (2l+1)*(l+1)  — only nloc >= l kept

// scratch (static device globals — allowed)
__device__ float2 g_fhat [NSPEC*16*16];     // [s][b][i]
__device__ float2 g_psi  [NSPEC*16*64];     // [s][i][o]
__device__ float2 g_Fz   [1024*NPACK];      // [b*64+o][packed e]  (23.4 MB)
__device__ float  g_wig3p[32*NPACK];        // packed wig_so3

__constant__ int c_offs[16] = {0,1,10,35,84,165,286,455,680,969,1330,1771,2300,2925,3654,4495};
__constant__ int c_offP[16] = {0,1,7,22,50,95,161,252,372,525,715,946,1222,1547,1925,2360};

// ---------------- Kernel 1: fhat[s,b,f] = sum_j wig_s2[j,s] * DFT_alpha(x)[b,f,j,m(s)] ----------------
__global__ void k_fhat(const float* __restrict__ x, const float* __restrict__ wig) {
    __shared__ float  sx[64*65];
    __shared__ float2 xf[64*31];       // [j][mt], mt = m+15
    __shared__ float  c64[64], s64[64];
    int b = blockIdx.x, f = blockIdx.y, tid = threadIdx.x;
    if (tid < 64) { float sv, cv; sincospif((float)tid/32.0f, &sv, &cv); c64[tid]=cv; s64[tid]=sv; }
    const float* xp = x + (size_t)(b*16+f)*4096;
    for (int p = tid; p < 4096; p += 256) sx[(p>>6)*65 + (p&63)] = xp[p];
    __syncthreads();
    for (int p = tid; p < 1984; p += 256) {           // 31 m-values x 64 betas
        int mt = p >> 6, j = p & 63, m = mt - 15;
        float ar=0.f, ai=0.f;
        const float* row = &sx[j*65];
        #pragma unroll 8
        for (int a = 0; a < 64; a++) {
            int t = (m*a) & 63;
            float v = row[a];
            ar += v*c64[t];                            // e^{-2pi i m a/64}
            ai -= v*s64[t];
        }
        xf[j*31+mt] = make_float2(ar, ai);
    }
    __syncthreads();
    int s = tid;
    int l = (int)sqrtf((float)s);
    while ((l+1)*(l+1) <= s) ++l;
    while (l*l > s) --l;
    int mt = s - l*l - l + 15;
    float ar=0.f, ai=0.f;
    #pragma unroll 8
    for (int j = 0; j < 64; j++) {
        float w = wig[j*NSPEC + s];
        float2 v = xf[j*31+mt];
        ar += w*v.x; ai += w*v.y;
    }
    g_fhat[(s*16+b)*16+f] = make_float2(ar, ai);
}

// ---------------- Kernel 2: psi[s,i,o] = scaling * sum_g kernel[i,o,g] * Fk[s,g] ----------------
__global__ void k_psi(const float* __restrict__ kern, const float* __restrict__ fkr,
                      const float* __restrict__ fki, float scaling) {
    __shared__ float2 fk[32];
    int s = blockIdx.x, tid = threadIdx.x;
    if (tid < 32) fk[tid] = make_float2(fkr[s*32+tid]*scaling, fki[s*32+tid]*scaling);
    __syncthreads();
    for (int p = tid; p < 1024; p += 256) {            // p = i*64+o
        const float* kp = kern + p*32;
        float ar=0.f, ai=0.f;
        #pragma unroll
        for (int g = 0; g < 32; g++) { float kv = kp[g]; ar += kv*fk[g].x; ai += kv*fk[g].y; }
        g_psi[s*1024 + p] = make_float2(ar, ai);
    }
}

// ---------------- Kernel 2b: pack wig_so3 to nloc>=l layout ----------------
__global__ void k_pack(const float* __restrict__ wig3) {
    int k = blockIdx.x, tid = threadIdx.x;
    for (int p = tid; p < NPACK; p += 256) {
        int l = 15;
        while (c_offP[l] > p) --l;
        int r = p - c_offP[l];
        int mloc = r / (l+1);
        int nq   = r - mloc*(l+1);
        g_wig3p[k*NPACK + p] = wig3[k*NSPEC3 + c_offs[l] + mloc*(2*l+1) + (nq + l)];
    }
}

// ---------------- Kernel 3: packed Fz (only n >= 0) ----------------
__global__ void k_fz() {
    extern __shared__ float2 sm3[];
    float2* fh = sm3;          // [s*16+i]
    float2* ps = sm3 + 4096;   // [s*16+i]
    int bo = blockIdx.x, b = bo >> 6, o = bo & 63, tid = threadIdx.x;
    for (int p = tid; p < 4096; p += 256) {
        int s = p >> 4, i = p & 15;
        fh[p] = g_fhat[(s*16+b)*16 + i];
        ps[p] = g_psi [(s*16+i)*64 + o];
    }
    __syncthreads();
    for (int e = tid; e < NPACK; e += 256) {
        int l = 15;
        while (c_offP[l] > e) --l;
        int r = e - c_offP[l];
        int mloc = r / (l+1);
        int nq   = r - mloc*(l+1);
        int nloc = nq + l;
        const float2* fp = &fh[(l*l + mloc)*16];
        const float2* pp = &ps[(l*l + nloc)*16];
        float ar=0.f, ai=0.f;
        #pragma unroll
        for (int i = 0; i < 16; i++) {
            float2 a = fp[i], c = pp[i];
            ar += a.x*c.x + a.y*c.y;                   // fhat * conj(psi)
            ai += a.y*c.x - a.x*c.y;
        }
        g_Fz[(size_t)bo*NPACK + e] = make_float2(ar, ai);
    }
}

// ---------------- Kernel 4 (fused, Hermitian-half): spec(n>=0) + 2D synthesis ----------------
// grid (1024 bo, 4 kq); each block handles 8 beta_out values.
// smem float2 units: Fz 2856 | spc 496 [mi*16+nq] | Vv 512 [a*16+nq] | cs 992 | wk float 2856
// total = (2856+496+512+992)*8 + 2856*4 = 38848 + 11424 = 50272 B -> 4 CTAs/SM
__global__ void k_main(const float* __restrict__ bias, float* __restrict__ out) {
    extern __shared__ float smraw[];
    float2* Fz  = (float2*)smraw;     // 2856
    float2* spc = Fz  + 2856;         // 496
    float2* Vv  = spc + 496;          // 512
    float2* cs  = Vv  + 512;          // 992: cs[q*32+r] = e^{+2pi i (q-15) r/32}; 16B-aligned
    float*  wk  = (float*)(cs + 992); // 2856
    int tid = threadIdx.x;
    int bo = blockIdx.x, o = bo & 63;
    int kq = blockIdx.y;
    int w = tid >> 5, lane = tid & 31;

    for (int p = tid; p < 992; p += 256) {
        int q = p >> 5, r = p & 31;
        int t = ((q-15)*r) & 31;
        float sv, cv; sincospif((float)t / 16.0f, &sv, &cv);
        cs[p] = make_float2(cv, sv);
    }
    for (int p = tid; p < NPACK; p += 256) Fz[p] = g_Fz[(size_t)bo*NPACK + p];
    float bv = bias[o];

    // stage-1 thread mapping: q = tid>>4 (a-pair: a=2q,2q+1), n = tid&15
    int s1q = tid >> 4, s1n = tid & 15;

    for (int kk = 0; kk < 8; kk++) {
        int k = kq*8 + kk;
        __syncthreads();
        for (int p = tid; p < NPACK; p += 256) wk[p] = g_wig3p[k*NPACK + p];
        __syncthreads();

        // spec[m,n] for n>=0: sum_{l>=max(|m|,n)} Fz_packed * d_packed
        for (int p = tid; p < 496; p += 256) {
            int mi = p >> 4, nq = p & 15;
            int m = mi - 15;
            int am = m < 0 ? -m : m;
            int lmin = am > nq ? am : nq;
            float ar = 0.f, ai = 0.f;
            for (int l = lmin; l < 16; l++) {
                int idx = c_offP[l] + (m+l)*(l+1) + nq;
                float d = wk[idx];
                float2 fz = Fz[idx];
                ar += fz.x*d;
                ai += fz.y*d;
            }
            spc[p] = make_float2(ar, ai);
        }
        __syncthreads();

        // stage 1: V[a][n] = sum_m spec[m,n] e^{+2pi i m a/32}, n=0..15 only
        {
            int a0 = 2*s1q;                          // a in {a0, a0+1}
            float vr0=0,vi0=0,vr1=0,vi1=0;
            const float4* cs4 = (const float4*)cs;
            #pragma unroll
            for (int mi = 0; mi < 31; mi++) {
                float2 sp = spc[mi*16 + s1n];
                float4 e = cs4[mi*16 + s1q];         // (e_a0.x, e_a0.y, e_a1.x, e_a1.y)
                vr0 += sp.x*e.x - sp.y*e.y; vi0 += sp.x*e.y + sp.y*e.x;
                vr1 += sp.x*e.z - sp.y*e.w; vi1 += sp.x*e.w + sp.y*e.z;
            }
            Vv[(a0+0)*16 + s1n] = make_float2(vr0,vi0);
            Vv[(a0+1)*16 + s1n] = make_float2(vr1,vi1);
        }
        __syncthreads();

        // stage 2: out[a,g] = bv + V[a][0].re + 2*sum_{n=1..15}(V.re*cos - V.im*sin)
        {
            int a0 = w*4, g = lane;
            float s0=0.f, s1=0.f, s2=0.f, s3=0.f;
            #pragma unroll
            for (int n = 1; n < 16; n++) {
                float2 e  = cs[(n+15)*32 + g];       // e^{+2pi i n g/32}
                float2 v0 = Vv[(a0+0)*16+n];
                float2 v1 = Vv[(a0+1)*16+n];
                float2 v2 = Vv[(a0+2)*16+n];
                float2 v3 = Vv[(a0+3)*16+n];
                s0 += v0.x*e.x - v0.y*e.y;
                s1 += v1.x*e.x - v1.y*e.y;
                s2 += v2.x*e.x - v2.y*e.y;
                s3 += v3.x*e.x - v3.y*e.y;
            }
            size_t base = ((size_t)bo*32 + k)*1024;
            out[base + (a0+0)*32 + g] = bv + Vv[(a0+0)*16].x + 2.f*s0;
            out[base + (a0+1)*32 + g] = bv + Vv[(a0+1)*16].x + 2.f*s1;
            out[base + (a0+2)*32 + g] = bv + Vv[(a0+2)*16].x + 2.f*s2;
            out[base + (a0+3)*32 + g] = bv + Vv[(a0+3)*16].x + 2.f*s3;
        }
    }
}

extern "C" void kernel_launch(void* const* d_in, const int* in_sizes, int n_in,
                              void* d_out, int out_size) {
    const float* x       = (const float*)d_in[0];
    const float* kern    = (const float*)d_in[1];
    const float* bias    = (const float*)d_in[2];
    const float* wig_s2  = (const float*)d_in[3];
    const float* fk_re   = (const float*)d_in[4];
    const float* fk_im   = (const float*)d_in[5];
    const float* wig_so3 = (const float*)d_in[6];
    float* out = (float*)d_out;

    float scaling = 1.0f / sqrtf(32768.0f);

    cudaFuncSetAttribute(k_fz,   cudaFuncAttributeMaxDynamicSharedMemorySize, 65536);
    cudaFuncSetAttribute(k_main, cudaFuncAttributeMaxDynamicSharedMemorySize, 50272);

    k_fhat<<<dim3(16,16), 256>>>(x, wig_s2);
    k_psi <<<256, 256>>>(kern, fk_re, fk_im, scaling);
    k_pack<<<32, 256>>>(wig_so3);
    k_fz  <<<1024, 256, 65536>>>();
    k_main<<<dim3(1024, 4), 256, 50272>>>(bias, out);
}

// round 4
// speedup vs baseline: 2.9887x; 1.3673x over previous
#include <cuda_runtime.h>
#include <math.h>

#define NSPEC  256
#define NSPEC3 5456
#define NPACK  2856   // sum over l of (2l+1)*(l+1)  — only nloc >= l kept

// scratch (static device globals — allowed)
__device__ float2 g_fhat [16*16*NSPEC];     // [b][f][s]
__device__ float2 g_psi  [16*64*NSPEC];     // [i][o][s]
__device__ float2 g_Fz   [1024*NPACK];      // [b*64+o][packed e]  (23.4 MB)
__device__ float  g_wig3p[32*NPACK];        // packed wig_so3

__constant__ int c_offs[16] = {0,1,10,35,84,165,286,455,680,969,1330,1771,2300,2925,3654,4495};
__constant__ int c_offP[16] = {0,1,7,22,50,95,161,252,372,525,715,946,1222,1547,1925,2360};

// ---------------- Kernel 1: fhat[b,f,s] = sum_j wig_s2[j,s] * DFT_alpha(x)[b,f,j,m(s)] ----------------
__global__ void k_fhat(const float* __restrict__ x, const float* __restrict__ wig) {
    __shared__ float  sx[64*65];
    __shared__ float2 xf[64*31];       // [j][mt], mt = m+15
    __shared__ float  c64[64], s64[64];
    int b = blockIdx.x, f = blockIdx.y, tid = threadIdx.x;
    if (tid < 64) { float sv, cv; sincospif((float)tid/32.0f, &sv, &cv); c64[tid]=cv; s64[tid]=sv; }
    const float* xp = x + (size_t)(b*16+f)*4096;
    for (int p = tid; p < 4096; p += 256) sx[(p>>6)*65 + (p&63)] = xp[p];
    __syncthreads();
    for (int p = tid; p < 1984; p += 256) {           // 31 m-values x 64 betas
        int mt = p >> 6, j = p & 63, m = mt - 15;
        float ar=0.f, ai=0.f;
        const float* row = &sx[j*65];
        #pragma unroll 8
        for (int a = 0; a < 64; a++) {
            int t = (m*a) & 63;
            float v = row[a];
            ar += v*c64[t];                            // e^{-2pi i m a/64}
            ai -= v*s64[t];
        }
        xf[j*31+mt] = make_float2(ar, ai);
    }
    __syncthreads();
    int s = tid;
    int l = (int)sqrtf((float)s);
    while ((l+1)*(l+1) <= s) ++l;
    while (l*l > s) --l;
    int mt = s - l*l - l + 15;
    float ar=0.f, ai=0.f;
    #pragma unroll 8
    for (int j = 0; j < 64; j++) {
        float w = wig[j*NSPEC + s];
        float2 v = xf[j*31+mt];
        ar += w*v.x; ai += w*v.y;
    }
    g_fhat[(b*16+f)*NSPEC + s] = make_float2(ar, ai);  // coalesced over s
}

// ---------------- Kernel 2: psi[i,o,s] = scaling * sum_g kernel[i,o,g] * Fk[s,g] ----------------
__global__ void k_psi(const float* __restrict__ kern, const float* __restrict__ fkr,
                      const float* __restrict__ fki, float scaling) {
    __shared__ float2 fk[32];
    int s = blockIdx.x, tid = threadIdx.x;
    if (tid < 32) fk[tid] = make_float2(fkr[s*32+tid]*scaling, fki[s*32+tid]*scaling);
    __syncthreads();
    for (int p = tid; p < 1024; p += 256) {            // p = i*64+o
        const float* kp = kern + p*32;
        float ar=0.f, ai=0.f;
        #pragma unroll
        for (int g = 0; g < 32; g++) { float kv = kp[g]; ar += kv*fk[g].x; ai += kv*fk[g].y; }
        g_psi[p*NSPEC + s] = make_float2(ar, ai);
    }
}

// ---------------- Kernel 2b: pack wig_so3 to nloc>=l layout ----------------
__global__ void k_pack(const float* __restrict__ wig3) {
    int k = blockIdx.x, tid = threadIdx.x;
    for (int p = tid; p < NPACK; p += 256) {
        int l = 15;
        while (c_offP[l] > p) --l;
        int r = p - c_offP[l];
        int mloc = r / (l+1);
        int nq   = r - mloc*(l+1);
        g_wig3p[k*NPACK + p] = wig3[k*NSPEC3 + c_offs[l] + mloc*(2*l+1) + (nq + l)];
    }
}

// ---------------- Kernel 3: packed Fz (only n >= 0), conflict-free [i][s] smem layout ----------------
__global__ void k_fz() {
    extern __shared__ float2 sm3[];
    float2* fh = sm3;          // [i*256+s]
    float2* ps = sm3 + 4096;   // [i*256+s]
    int bo = blockIdx.x, b = bo >> 6, o = bo & 63, tid = threadIdx.x;
    for (int p = tid; p < 4096; p += 256) {
        int i = p >> 8, s = p & 255;
        fh[p] = g_fhat[(b*16+i)*NSPEC + s];            // coalesced
        ps[p] = g_psi [(i*64+o)*NSPEC + s];            // coalesced
    }
    __syncthreads();
    for (int e = tid; e < NPACK; e += 256) {
        int l = 15;
        while (c_offP[l] > e) --l;
        int r = e - c_offP[l];
        int mloc = r / (l+1);
        int nq   = r - mloc*(l+1);
        int sm_ = l*l + mloc;
        int sn  = l*l + nq + l;
        float ar=0.f, ai=0.f;
        #pragma unroll
        for (int i = 0; i < 16; i++) {
            float2 a = fh[i*256 + sm_];                // near-broadcast
            float2 c = ps[i*256 + sn];                 // stride-1 across threads
            ar += a.x*c.x + a.y*c.y;                   // fhat * conj(psi)
            ai += a.y*c.x - a.x*c.y;
        }
        g_Fz[(size_t)bo*NPACK + e] = make_float2(ar, ai);
    }
}

// ---------------- Kernel 4 (fused, Hermitian + radix-2): spec(n>=0) + 2D synthesis ----------------
// grid (1024 bo, 4 kq); each block handles 8 beta_out values.
// smem float2 units: Fz 2856 | spc 496 [mi*16+nq] | Vv 512 [a*16+nq] | cs 992
// total = (2856+496+512+992)*8 = 38848 B -> 5 CTAs/SM
__global__ void k_main(const float* __restrict__ bias, float* __restrict__ out) {
    extern __shared__ float smraw[];
    float2* Fz  = (float2*)smraw;     // 2856
    float2* spc = Fz  + 2856;         // 496
    float2* Vv  = spc + 496;          // 512
    float2* cs  = Vv  + 512;          // 992: cs[q*32+r] = e^{+2pi i (q-15) r/32}
    int tid = threadIdx.x;
    int bo = blockIdx.x, o = bo & 63;
    int kq = blockIdx.y;

    for (int p = tid; p < 992; p += 256) {
        int q = p >> 5, r = p & 31;
        int t = ((q-15)*r) & 31;
        float sv, cv; sincospif((float)t / 16.0f, &sv, &cv);
        cs[p] = make_float2(cv, sv);
    }
    for (int p = tid; p < NPACK; p += 256) Fz[p] = g_Fz[(size_t)bo*NPACK + p];
    float bv = bias[o];

    int hi = tid >> 4, lo = tid & 15;   // stage1: (aa=hi, n=lo); stage2: (a2=hi, g=lo)

    for (int kk = 0; kk < 8; kk++) {
        int k = kq*8 + kk;
        __syncthreads();                               // prior stage2 done before spc/Vv rewrite

        // spec[m,n] for n>=0: sum_{l>=max(|m|,n)} Fz_packed * d_packed (wigner direct from L1/L2)
        const float* wkg = g_wig3p + k*NPACK;
        for (int p = tid; p < 496; p += 256) {
            int mi = p >> 4, nq = p & 15;
            int m = mi - 15;
            int am = m < 0 ? -m : m;
            int lmin = am > nq ? am : nq;
            float ar = 0.f, ai = 0.f;
            for (int l = lmin; l < 16; l++) {
                int idx = c_offP[l] + (m+l)*(l+1) + nq;
                float d = __ldg(&wkg[idx]);
                float2 fz = Fz[idx];
                ar += fz.x*d;
                ai += fz.y*d;
            }
            spc[p] = make_float2(ar, ai);
        }
        __syncthreads();

        // stage 1 (radix-2 over m): V[aa][n], V[aa+16][n] from even/odd-m partial sums
        {
            float er=0.f, ei=0.f, odr=0.f, odi=0.f;
            #pragma unroll
            for (int mi = 0; mi < 31; mi++) {
                float2 sp = spc[mi*16 + lo];
                float2 e  = cs[mi*32 + hi];            // e^{+2pi i (mi-15) aa/32}, broadcast
                float tr = sp.x*e.x - sp.y*e.y;
                float ti = sp.x*e.y + sp.y*e.x;
                if (((mi - 15) & 1) == 0) { er += tr; ei += ti; }
                else                      { odr += tr; odi += ti; }
            }
            Vv[ hi      *16 + lo] = make_float2(er + odr, ei + odi);
            Vv[(hi + 16)*16 + lo] = make_float2(er - odr, ei - odi);
        }
        __syncthreads();

        // stage 2 (radix-2 over n): out[a][g], out[a][g+16]
        {
            size_t base = ((size_t)bo*32 + k)*1024;
            #pragma unroll
            for (int da = 0; da < 2; da++) {
                int a = hi*2 + da;
                float se = 0.f, so = 0.f;
                #pragma unroll
                for (int n = 1; n < 16; n++) {
                    float2 v = Vv[a*16 + n];           // broadcast
                    float2 e = cs[(n+15)*32 + lo];     // e^{+2pi i n g/32}
                    float t = v.x*e.x - v.y*e.y;
                    if (n & 1) so += t; else se += t;
                }
                float c0 = bv + Vv[a*16].x;
                out[base + a*32 + lo     ] = c0 + 2.f*(se + so);
                out[base + a*32 + lo + 16] = c0 + 2.f*(se - so);
            }
        }
    }
}

extern "C" void kernel_launch(void* const* d_in, const int* in_sizes, int n_in,
                              void* d_out, int out_size) {
    const float* x       = (const float*)d_in[0];
    const float* kern    = (const float*)d_in[1];
    const float* bias    = (const float*)d_in[2];
    const float* wig_s2  = (const float*)d_in[3];
    const float* fk_re   = (const float*)d_in[4];
    const float* fk_im   = (const float*)d_in[5];
    const float* wig_so3 = (const float*)d_in[6];
    float* out = (float*)d_out;

    float scaling = 1.0f / sqrtf(32768.0f);

    cudaFuncSetAttribute(k_fz,   cudaFuncAttributeMaxDynamicSharedMemorySize, 65536);
    cudaFuncSetAttribute(k_main, cudaFuncAttributeMaxDynamicSharedMemorySize, 38848);

    k_fhat<<<dim3(16,16), 256>>>(x, wig_s2);
    k_psi <<<256, 256>>>(kern, fk_re, fk_im, scaling);
    k_pack<<<32, 256>>>(wig_so3);
    k_fz  <<<1024, 256, 65536>>>();
    k_main<<<dim3(1024, 4), 256, 38848>>>(bias, out);
}

// round 5
// speedup vs baseline: 3.4289x; 1.1473x over previous
#include <cuda_runtime.h>
#include <math.h>

#define NSPEC  256
#define NSPEC3 5456
#define NPACK  2856   // sum over l of (2l+1)*(l+1)  — only nloc >= l kept

// scratch (static device globals — allowed)
__device__ float2 g_fhat [16*16*NSPEC];     // [b][f][s]
__device__ float2 g_psi  [16*64*NSPEC];     // [i][o][s]
__device__ float2 g_Fz   [1024*NPACK];      // [b*64+o][packed e]  (23.4 MB)
__device__ float  g_wig3p[32*NPACK];        // packed wig_so3

__constant__ int c_offs[16] = {0,1,10,35,84,165,286,455,680,969,1330,1771,2300,2925,3654,4495};
__constant__ int c_offP[16] = {0,1,7,22,50,95,161,252,372,525,715,946,1222,1547,1925,2360};

// ---------------- Kernel 1: fhat[b,f,s] = sum_j wig_s2[j,s] * DFT_alpha(x)[b,f,j,m(s)] ----------------
__global__ void k_fhat(const float* __restrict__ x, const float* __restrict__ wig) {
    __shared__ float  sx[64*65];
    __shared__ float2 xf[64*31];       // [j][mt], mt = m+15
    __shared__ float  c64[64], s64[64];
    int b = blockIdx.x, f = blockIdx.y, tid = threadIdx.x;
    if (tid < 64) { float sv, cv; sincospif((float)tid/32.0f, &sv, &cv); c64[tid]=cv; s64[tid]=sv; }
    const float* xp = x + (size_t)(b*16+f)*4096;
    for (int p = tid; p < 4096; p += 256) sx[(p>>6)*65 + (p&63)] = xp[p];
    __syncthreads();
    for (int p = tid; p < 1984; p += 256) {           // 31 m-values x 64 betas
        int mt = p >> 6, j = p & 63, m = mt - 15;
        float ar=0.f, ai=0.f;
        const float* row = &sx[j*65];
        #pragma unroll 8
        for (int a = 0; a < 64; a++) {
            int t = (m*a) & 63;
            float v = row[a];
            ar += v*c64[t];                            // e^{-2pi i m a/64}
            ai -= v*s64[t];
        }
        xf[j*31+mt] = make_float2(ar, ai);
    }
    __syncthreads();
    int s = tid;
    int l = (int)sqrtf((float)s);
    while ((l+1)*(l+1) <= s) ++l;
    while (l*l > s) --l;
    int mt = s - l*l - l + 15;
    float ar=0.f, ai=0.f;
    #pragma unroll 8
    for (int j = 0; j < 64; j++) {
        float w = wig[j*NSPEC + s];
        float2 v = xf[j*31+mt];
        ar += w*v.x; ai += w*v.y;
    }
    g_fhat[(b*16+f)*NSPEC + s] = make_float2(ar, ai);
}

// ---------------- Kernel 2: psi[i,o,s] = scaling * sum_g kernel[i,o,g] * Fk[s,g] ----------------
__global__ void k_psi(const float* __restrict__ kern, const float* __restrict__ fkr,
                      const float* __restrict__ fki, float scaling) {
    __shared__ float2 fk[32];
    int s = blockIdx.x, tid = threadIdx.x;
    if (tid < 32) fk[tid] = make_float2(fkr[s*32+tid]*scaling, fki[s*32+tid]*scaling);
    __syncthreads();
    for (int p = tid; p < 1024; p += 256) {            // p = i*64+o
        const float* kp = kern + p*32;
        float ar=0.f, ai=0.f;
        #pragma unroll
        for (int g = 0; g < 32; g++) { float kv = kp[g]; ar += kv*fk[g].x; ai += kv*fk[g].y; }
        g_psi[p*NSPEC + s] = make_float2(ar, ai);
    }
}

// ---------------- Kernel 2b: pack wig_so3 to nloc>=l layout ----------------
__global__ void k_pack(const float* __restrict__ wig3) {
    int k = blockIdx.x, tid = threadIdx.x;
    for (int p = tid; p < NPACK; p += 256) {
        int l = 15;
        while (c_offP[l] > p) --l;
        int r = p - c_offP[l];
        int mloc = r / (l+1);
        int nq   = r - mloc*(l+1);
        g_wig3p[k*NPACK + p] = wig3[k*NSPEC3 + c_offs[l] + mloc*(2*l+1) + (nq + l)];
    }
}

// ---------------- Kernel 3: packed Fz (only n >= 0), conflict-free [i][s] smem layout ----------------
__global__ void k_fz() {
    extern __shared__ float2 sm3[];
    float2* fh = sm3;          // [i*256+s]
    float2* ps = sm3 + 4096;   // [i*256+s]
    int bo = blockIdx.x, b = bo >> 6, o = bo & 63, tid = threadIdx.x;
    for (int p = tid; p < 4096; p += 512) {
        int i = p >> 8, s = p & 255;
        fh[p] = g_fhat[(b*16+i)*NSPEC + s];            // coalesced
        ps[p] = g_psi [(i*64+o)*NSPEC + s];            // coalesced
    }
    __syncthreads();
    for (int e = tid; e < NPACK; e += 512) {
        int l = 15;
        while (c_offP[l] > e) --l;
        int r = e - c_offP[l];
        int mloc = r / (l+1);
        int nq   = r - mloc*(l+1);
        int sm_ = l*l + mloc;
        int sn  = l*l + nq + l;
        float ar=0.f, ai=0.f;
        #pragma unroll
        for (int i = 0; i < 16; i++) {
            float2 a = fh[i*256 + sm_];
            float2 c = ps[i*256 + sn];
            ar += a.x*c.x + a.y*c.y;                   // fhat * conj(psi)
            ai += a.y*c.x - a.x*c.y;
        }
        g_Fz[(size_t)bo*NPACK + e] = make_float2(ar, ai);
    }
}

// ---------------- Kernel 4 (fused, Hermitian + radix-4, dual-k): spec(n>=0) + 2D synthesis ----------------
// grid (1024 bo, 4 kq); each block handles 8 beta_out values, 2 at a time.
// smem float2 units: Fz 2856 | spc 992 (2 planes) | Vv 1024 (2 planes) | cs16 496
// total = (2856+992+1024+496)*8 = 42944 B -> 5 CTAs/SM
__global__ void k_main(const float* __restrict__ bias, float* __restrict__ out) {
    extern __shared__ float smraw[];
    float2* Fz   = (float2*)smraw;     // 2856
    float2* spc  = Fz  + 2856;         // 992:  [kp*496 + mi*16 + nq]
    float2* Vv   = spc + 992;          // 1024: [kp*512 + a*16 + nq]
    float2* cs16 = Vv  + 1024;         // 496:  cs16[q*16+r] = e^{+2pi i (q-15) r/32}, r<16
    int tid = threadIdx.x;
    int bo = blockIdx.x, o = bo & 63;
    int kq = blockIdx.y;

    for (int p = tid; p < 496; p += 256) {
        int q = p >> 4, r = p & 15;
        int t = ((q-15)*r) & 31;
        float sv, cv; sincospif((float)t / 16.0f, &sv, &cv);
        cs16[p] = make_float2(cv, sv);
    }
    for (int p = tid; p < NPACK; p += 256) Fz[p] = g_Fz[(size_t)bo*NPACK + p];
    float bv = bias[o];

    int kp = tid >> 7, t2 = tid & 127;

    for (int kk4 = 0; kk4 < 4; kk4++) {
        int k = kq*8 + kk4*2 + kp;
        __syncthreads();                               // prior stage2 done before spc/Vv rewrite

        // spec[m,n] for n>=0 (half-block per k-plane)
        const float* wkg = g_wig3p + k*NPACK;
        for (int p = t2; p < 496; p += 128) {
            int mi = p >> 4, nq = p & 15;
            int m = mi - 15;
            int am = m < 0 ? -m : m;
            int lmin = am > nq ? am : nq;
            float ar = 0.f, ai = 0.f;
            for (int l = lmin; l < 16; l++) {
                int idx = c_offP[l] + (m+l)*(l+1) + nq;
                float d = __ldg(&wkg[idx]);
                float2 fz = Fz[idx];
                ar += fz.x*d;
                ai += fz.y*d;
            }
            spc[kp*496 + p] = make_float2(ar, ai);
        }
        __syncthreads();

        // stage 1 (radix-4 over m): 31 cmacs -> V[a0], V[a0+8], V[a0+16], V[a0+24]
        {
            int a0 = t2 >> 4, n = t2 & 15;             // a0 in 0..7
            float s0r=0,s0i=0,s1r=0,s1i=0,s2r=0,s2i=0,s3r=0,s3i=0;
            #pragma unroll
            for (int mi = 0; mi < 31; mi++) {
                float2 sp = spc[kp*496 + mi*16 + n];
                float2 e  = cs16[mi*16 + a0];          // e^{+2pi i (mi-15) a0/32}
                float tr = sp.x*e.x - sp.y*e.y;
                float ti = sp.x*e.y + sp.y*e.x;
                int r = (mi + 1) & 3;                  // (mi-15) mod 4
                if      (r == 0) { s0r += tr; s0i += ti; }
                else if (r == 1) { s1r += tr; s1i += ti; }
                else if (r == 2) { s2r += tr; s2i += ti; }
                else             { s3r += tr; s3i += ti; }
            }
            float2* V = Vv + kp*512;
            V[(a0     )*16 + n] = make_float2(s0r + s1r + s2r + s3r,  s0i + s1i + s2i + s3i);
            V[(a0 +  8)*16 + n] = make_float2(s0r - s1i - s2r + s3i,  s0i + s1r - s2i - s3r);
            V[(a0 + 16)*16 + n] = make_float2(s0r - s1r + s2r - s3r,  s0i - s1i + s2i - s3i);
            V[(a0 + 24)*16 + n] = make_float2(s0r + s1i - s2r - s3i,  s0i - s1r - s2i + s3r);
        }
        __syncthreads();

        // stage 2 (radix-2 over n): out[a][g], out[a][g+16]; 4 a-values per thread
        {
            int hi = t2 >> 4, lo = t2 & 15;            // hi in 0..7, g = lo
            const float2* V = Vv + kp*512;
            size_t base = ((size_t)bo*32 + k)*1024;
            #pragma unroll
            for (int da = 0; da < 4; da++) {
                int a = hi*4 + da;
                float se = 0.f, so = 0.f;
                #pragma unroll
                for (int n = 1; n < 16; n++) {
                    float2 v = V[a*16 + n];            // broadcast
                    float2 e = cs16[(n+15)*16 + lo];   // e^{+2pi i n g/32}
                    float t = v.x*e.x - v.y*e.y;
                    if (n & 1) so += t; else se += t;
                }
                float c0 = bv + V[a*16].x;
                out[base + a*32 + lo     ] = c0 + 2.f*(se + so);
                out[base + a*32 + lo + 16] = c0 + 2.f*(se - so);
            }
        }
    }
}

extern "C" void kernel_launch(void* const* d_in, const int* in_sizes, int n_in,
                              void* d_out, int out_size) {
    const float* x       = (const float*)d_in[0];
    const float* kern    = (const float*)d_in[1];
    const float* bias    = (const float*)d_in[2];
    const float* wig_s2  = (const float*)d_in[3];
    const float* fk_re   = (const float*)d_in[4];
    const float* fk_im   = (const float*)d_in[5];
    const float* wig_so3 = (const float*)d_in[6];
    float* out = (float*)d_out;

    float scaling = 1.0f / sqrtf(32768.0f);

    cudaFuncSetAttribute(k_fz,   cudaFuncAttributeMaxDynamicSharedMemorySize, 65536);
    cudaFuncSetAttribute(k_main, cudaFuncAttributeMaxDynamicSharedMemorySize, 42944);

    k_fhat<<<dim3(16,16), 256>>>(x, wig_s2);
    k_psi <<<256, 256>>>(kern, fk_re, fk_im, scaling);
    k_pack<<<32, 256>>>(wig_so3);
    k_fz  <<<1024, 512, 65536>>>();
    k_main<<<dim3(1024, 4), 256, 42944>>>(bias, out);
}